// round 1
// baseline (speedup 1.0000x reference)
#include <cuda_runtime.h>
#include <cuda_bf16.h>
#include <cstdint>

#define N_NODES 50000
#define N_EDGES 600000

// ---------------- scratch (static __device__, no allocations) ----------------
__device__ int   g_src[N_EDGES];
__device__ int   g_dst[N_EDGES];
__device__ float g_deg[50048];                    // padded to mult of 4 for float4 zeroing
__device__ float g_invdeg[N_NODES];
__device__ float g_agg[(size_t)N_NODES * 128];
__device__ float g_h1[(size_t)N_NODES * 128];
__device__ float g_h2[(size_t)N_NODES * 128];
__device__ float g_B[256 * 128];                  // concatenated [wn; wr]^T  (k-major)
__device__ int   g_is64;

// ---------------- utility kernels ----------------
__global__ void zero_kernel(float* p, int n4) {
    int i = blockIdx.x * blockDim.x + threadIdx.x;
    float4 z = make_float4(0.f, 0.f, 0.f, 0.f);
    for (; i < n4; i += gridDim.x * blockDim.x)
        ((float4*)p)[i] = z;
}

// Detect whether edge_index buffer is int64 (little-endian: odd 32-bit words == 0)
__global__ void detect_kernel(const unsigned int* p) {
    __shared__ int cnt;
    if (threadIdx.x == 0) cnt = 0;
    __syncthreads();
    int local = 0;
    for (int i = threadIdx.x; i < 2048; i += blockDim.x)
        if (p[2 * i + 1] == 0u) local++;
    atomicAdd(&cnt, local);
    __syncthreads();
    if (threadIdx.x == 0) g_is64 = (cnt > 1024) ? 1 : 0;
}

__global__ void convert_kernel(const void* p) {
    int e = blockIdx.x * blockDim.x + threadIdx.x;
    if (e >= N_EDGES) return;
    if (g_is64) {
        const long long* q = (const long long*)p;
        g_src[e] = (int)q[e];
        g_dst[e] = (int)q[N_EDGES + e];
    } else {
        const int* q = (const int*)p;
        g_src[e] = q[e];
        g_dst[e] = q[N_EDGES + e];
    }
}

__global__ void deg_kernel() {
    int e = blockIdx.x * blockDim.x + threadIdx.x;
    if (e >= N_EDGES) return;
    atomicAdd(&g_deg[g_dst[e]], 1.0f);
}

__global__ void invdeg_kernel() {
    int i = blockIdx.x * blockDim.x + threadIdx.x;
    if (i >= N_NODES) return;
    g_invdeg[i] = 1.0f / fmaxf(g_deg[i], 1.0f);
}

// ---------------- scatter: one warp per edge ----------------
__global__ void scatter_kernel(const float* __restrict__ X) {
    int gtid = blockIdx.x * blockDim.x + threadIdx.x;
    int warp = gtid >> 5;
    int lane = gtid & 31;
    if (warp >= N_EDGES) return;
    int s = g_src[warp];
    int d = g_dst[warp];
    const float4* xs = (const float4*)(X + (size_t)s * 128);
    float* ag = g_agg + (size_t)d * 128 + lane * 4;
    float4 v = xs[lane];
    atomicAdd(ag + 0, v.x);
    atomicAdd(ag + 1, v.y);
    atomicAdd(ag + 2, v.z);
    atomicAdd(ag + 3, v.w);
}

// ---------------- weight concat: B[k][o] = k<128 ? wn[o][k] : wr[o][k-128] ----------------
template <int OUT>
__global__ void prepB_kernel(const float* __restrict__ wn, const float* __restrict__ wr) {
    int idx = blockIdx.x * blockDim.x + threadIdx.x;
    if (idx >= 256 * OUT) return;
    int k = idx / OUT;
    int o = idx % OUT;
    g_B[idx] = (k < 128) ? wn[o * 128 + k] : wr[o * 128 + (k - 128)];
}

// ---------------- fused combine GEMM ----------------
// C[i][o] = act( sum_k A[i][k] * B[k][o] + bias[o] ),
// A[i][k] = k<128 ? g_agg[i][k]*g_invdeg[i] : X[i][k-128]
template <int OUT, bool RELU>
__global__ void __launch_bounds__(256) combine_kernel(const float* __restrict__ X,
                                                      const float* __restrict__ bias,
                                                      float* __restrict__ Cout) {
    constexpr int BM = 64, BK = 16;
    constexpr int TN = OUT / 16;                 // 8 (OUT=128) or 4 (OUT=64)
    __shared__ float As[BK][BM];
    __shared__ float Bs[BK][OUT];

    int tid = threadIdx.x;
    int tx  = tid & 15;
    int ty  = tid >> 4;
    int row0 = blockIdx.x * BM;

    float acc[4][TN];
#pragma unroll
    for (int m = 0; m < 4; m++)
#pragma unroll
        for (int n = 0; n < TN; n++) acc[m][n] = 0.f;

    int arow = tid >> 2;        // 0..63
    int akq  = tid & 3;         // float4 slot within 16-wide k tile

    for (int k0 = 0; k0 < 256; k0 += BK) {
        int grow = row0 + arow;
        float4 av = make_float4(0.f, 0.f, 0.f, 0.f);
        if (grow < N_NODES) {
            if (k0 < 128) {
                av = *(const float4*)(g_agg + (size_t)grow * 128 + k0 + akq * 4);
                float inv = g_invdeg[grow];
                av.x *= inv; av.y *= inv; av.z *= inv; av.w *= inv;
            } else {
                av = *(const float4*)(X + (size_t)grow * 128 + (k0 - 128) + akq * 4);
            }
        }
        As[akq * 4 + 0][arow] = av.x;
        As[akq * 4 + 1][arow] = av.y;
        As[akq * 4 + 2][arow] = av.z;
        As[akq * 4 + 3][arow] = av.w;

        constexpr int BF4 = BK * OUT / 4;
#pragma unroll
        for (int idx = tid; idx < BF4; idx += 256) {
            int kk = idx / (OUT / 4);
            int c4 = idx % (OUT / 4);
            ((float4*)&Bs[kk][0])[c4] = ((const float4*)(g_B + (size_t)(k0 + kk) * OUT))[c4];
        }
        __syncthreads();

#pragma unroll
        for (int kk = 0; kk < BK; kk++) {
            float4 a4 = *(const float4*)&As[kk][ty * 4];
            float af[4] = {a4.x, a4.y, a4.z, a4.w};
            float bf[TN];
            float4 b0 = *(const float4*)&Bs[kk][tx * 4];
            bf[0] = b0.x; bf[1] = b0.y; bf[2] = b0.z; bf[3] = b0.w;
            if constexpr (TN == 8) {
                float4 b1 = *(const float4*)&Bs[kk][64 + tx * 4];
                bf[4] = b1.x; bf[5] = b1.y; bf[6] = b1.z; bf[7] = b1.w;
            }
#pragma unroll
            for (int m = 0; m < 4; m++)
#pragma unroll
                for (int n = 0; n < TN; n++)
                    acc[m][n] = fmaf(af[m], bf[n], acc[m][n]);
        }
        __syncthreads();
    }

    float4 bv0 = *(const float4*)(bias + tx * 4);
    float4 bv1 = make_float4(0.f, 0.f, 0.f, 0.f);
    if constexpr (TN == 8) bv1 = *(const float4*)(bias + 64 + tx * 4);

#pragma unroll
    for (int m = 0; m < 4; m++) {
        int r = row0 + ty * 4 + m;
        if (r >= N_NODES) continue;
        float4 o0;
        o0.x = acc[m][0] + bv0.x;
        o0.y = acc[m][1] + bv0.y;
        o0.z = acc[m][2] + bv0.z;
        o0.w = acc[m][3] + bv0.w;
        if constexpr (RELU) {
            o0.x = fmaxf(o0.x, 0.f); o0.y = fmaxf(o0.y, 0.f);
            o0.z = fmaxf(o0.z, 0.f); o0.w = fmaxf(o0.w, 0.f);
        }
        *(float4*)(Cout + (size_t)r * OUT + tx * 4) = o0;
        if constexpr (TN == 8) {
            float4 o1;
            o1.x = acc[m][4] + bv1.x;
            o1.y = acc[m][5] + bv1.y;
            o1.z = acc[m][6] + bv1.z;
            o1.w = acc[m][7] + bv1.w;
            if constexpr (RELU) {
                o1.x = fmaxf(o1.x, 0.f); o1.y = fmaxf(o1.y, 0.f);
                o1.z = fmaxf(o1.z, 0.f); o1.w = fmaxf(o1.w, 0.f);
            }
            *(float4*)(Cout + (size_t)r * OUT + 64 + tx * 4) = o1;
        }
    }
}

// ---------------- host launch ----------------
extern "C" void kernel_launch(void* const* d_in, const int* in_sizes, int n_in,
                              void* d_out, int out_size) {
    const float* x   = (const float*)d_in[0];
    const void*  ei  = d_in[1];
    const float* w1n = (const float*)d_in[2];
    const float* w1r = (const float*)d_in[3];
    const float* b1  = (const float*)d_in[4];
    const float* w2n = (const float*)d_in[5];
    const float* w2r = (const float*)d_in[6];
    const float* b2  = (const float*)d_in[7];
    const float* w3n = (const float*)d_in[8];
    const float* w3r = (const float*)d_in[9];
    const float* b3  = (const float*)d_in[10];
    float* out = (float*)d_out;

    float *agg, *deg, *h1, *h2;
    cudaGetSymbolAddress((void**)&agg, g_agg);
    cudaGetSymbolAddress((void**)&deg, g_deg);
    cudaGetSymbolAddress((void**)&h1,  g_h1);
    cudaGetSymbolAddress((void**)&h2,  g_h2);

    const int TPB = 256;
    const int edgeBlocks    = (N_EDGES + TPB - 1) / TPB;
    const int scatterBlocks = (N_EDGES * 32 + TPB - 1) / TPB;
    const int gemmBlocks    = (N_NODES + 63) / 64;

    // structure (once per call)
    detect_kernel<<<1, 256>>>((const unsigned int*)ei);
    convert_kernel<<<edgeBlocks, TPB>>>(ei);
    zero_kernel<<<64, TPB>>>(deg, 50048 / 4);
    deg_kernel<<<edgeBlocks, TPB>>>();
    invdeg_kernel<<<(N_NODES + TPB - 1) / TPB, TPB>>>();

    // layer 1
    zero_kernel<<<512, TPB>>>(agg, (N_NODES * 128) / 4);
    scatter_kernel<<<scatterBlocks, TPB>>>(x);
    prepB_kernel<128><<<(256 * 128 + TPB - 1) / TPB, TPB>>>(w1n, w1r);
    combine_kernel<128, true><<<gemmBlocks, 256>>>(x, b1, h1);

    // layer 2
    zero_kernel<<<512, TPB>>>(agg, (N_NODES * 128) / 4);
    scatter_kernel<<<scatterBlocks, TPB>>>(h1);
    prepB_kernel<128><<<(256 * 128 + TPB - 1) / TPB, TPB>>>(w2n, w2r);
    combine_kernel<128, true><<<gemmBlocks, 256>>>(h1, b2, h2);

    // layer 3
    zero_kernel<<<512, TPB>>>(agg, (N_NODES * 128) / 4);
    scatter_kernel<<<scatterBlocks, TPB>>>(h2);
    prepB_kernel<64><<<(256 * 64 + TPB - 1) / TPB, TPB>>>(w3n, w3r);
    combine_kernel<64, false><<<gemmBlocks, 256>>>(h2, b3, out);
}

// round 3
// speedup vs baseline: 2.3418x; 2.3418x over previous
#include <cuda_runtime.h>
#include <cuda_bf16.h>
#include <cstdint>

#define N_NODES 50000
#define N_EDGES 600000

// ---------------- scratch (static __device__, no allocations) ----------------
__device__ int   g_src[N_EDGES];
__device__ int   g_dst[N_EDGES];
__device__ float g_deg[50048];
__device__ float g_invdeg[N_NODES];
__device__ float g_agg[(size_t)N_NODES * 128];
__device__ float g_h1[(size_t)N_NODES * 128];
__device__ float g_h2[(size_t)N_NODES * 128];
__device__ int   g_is64;

// ---------------- utility kernels ----------------
__global__ void zero_kernel(float* p, int n4) {
    int i = blockIdx.x * blockDim.x + threadIdx.x;
    float4 z = make_float4(0.f, 0.f, 0.f, 0.f);
    for (; i < n4; i += gridDim.x * blockDim.x)
        ((float4*)p)[i] = z;
}

__global__ void detect_kernel(const unsigned int* p) {
    __shared__ int cnt;
    if (threadIdx.x == 0) cnt = 0;
    __syncthreads();
    int local = 0;
    for (int i = threadIdx.x; i < 2048; i += blockDim.x)
        if (p[2 * i + 1] == 0u) local++;
    atomicAdd(&cnt, local);
    __syncthreads();
    if (threadIdx.x == 0) g_is64 = (cnt > 1024) ? 1 : 0;
}

__global__ void convert_kernel(const void* p) {
    int e = blockIdx.x * blockDim.x + threadIdx.x;
    if (e >= N_EDGES) return;
    if (g_is64) {
        const long long* q = (const long long*)p;
        g_src[e] = (int)q[e];
        g_dst[e] = (int)q[N_EDGES + e];
    } else {
        const int* q = (const int*)p;
        g_src[e] = q[e];
        g_dst[e] = q[N_EDGES + e];
    }
}

__global__ void deg_kernel() {
    int e = blockIdx.x * blockDim.x + threadIdx.x;
    if (e >= N_EDGES) return;
    atomicAdd(&g_deg[g_dst[e]], 1.0f);
}

__global__ void invdeg_kernel() {
    int i = blockIdx.x * blockDim.x + threadIdx.x;
    if (i >= N_NODES) return;
    g_invdeg[i] = 1.0f / fmaxf(g_deg[i], 1.0f);
}

// ---------------- scatter: one warp per edge, vector RED atomics ----------------
__global__ void scatter_kernel(const float* __restrict__ X) {
    int gtid = blockIdx.x * blockDim.x + threadIdx.x;
    int warp = gtid >> 5;
    int lane = gtid & 31;
    if (warp >= N_EDGES) return;
    int s = g_src[warp];
    int d = g_dst[warp];
    float4 v = ((const float4*)(X + (size_t)s * 128))[lane];
    float* ag = g_agg + (size_t)d * 128 + lane * 4;
    asm volatile("red.global.add.v4.f32 [%0], {%1, %2, %3, %4};"
                 :: "l"(ag), "f"(v.x), "f"(v.y), "f"(v.z), "f"(v.w) : "memory");
}

// ---------------- tf32 helpers ----------------
__device__ __forceinline__ uint32_t f2tf32(float f) {
    uint32_t o;
    asm("cvt.rna.tf32.f32 %0, %1;" : "=r"(o) : "f"(f));
    return o;
}
__device__ __forceinline__ void mma_tf32(float* d, const uint32_t* a, const uint32_t* b) {
    asm volatile(
        "mma.sync.aligned.m16n8k8.row.col.f32.tf32.tf32.f32 "
        "{%0,%1,%2,%3}, {%4,%5,%6,%7}, {%8,%9}, {%0,%1,%2,%3};"
        : "+f"(d[0]), "+f"(d[1]), "+f"(d[2]), "+f"(d[3])
        : "r"(a[0]), "r"(a[1]), "r"(a[2]), "r"(a[3]), "r"(b[0]), "r"(b[1]));
}

// ---------------- tensor-core combine GEMM (mma.sync tf32) ----------------
// C[i][o] = act( sum_{k<128} (agg[i][k]*invdeg[i]) * WN[o][k]
//             + sum_{k<128}  X[i][k] * WR[o][k] + bias[o] )
// CTA tile: 128 x OUT x 256. 8 warps = 4(m) x 2(n). Warp tile 32 x (OUT/2).
template <int OUT, bool RELU>
__global__ void __launch_bounds__(256) combine_mma(
    const float* __restrict__ X,
    const float* __restrict__ WN,
    const float* __restrict__ WR,
    const float* __restrict__ bias,
    float* __restrict__ Cout)
{
    constexpr int NA = OUT / 16;        // n-atoms per warp
    __shared__ uint32_t As[128][36];
    __shared__ uint32_t Bs[OUT][36];

    const int tid    = threadIdx.x;
    const int wid    = tid >> 5;
    const int lane   = tid & 31;
    const int warp_m = wid >> 1;
    const int warp_n = wid & 1;
    const int g      = lane >> 2;
    const int t      = lane & 3;
    const int row0   = blockIdx.x * 128;

    float acc[2][NA][4];
#pragma unroll
    for (int m = 0; m < 2; m++)
#pragma unroll
        for (int n = 0; n < NA; n++)
#pragma unroll
            for (int j = 0; j < 4; j++) acc[m][n][j] = 0.f;

    for (int c = 0; c < 8; c++) {
        const int k0 = c * 32;

#pragma unroll
        for (int i = 0; i < 4; i++) {
            int idx = i * 256 + tid;
            int r = idx >> 3, q = idx & 7;
            int grow = row0 + r;
            if (grow > N_NODES - 1) grow = N_NODES - 1;
            float4 v;
            if (k0 < 128) {
                v = *(const float4*)(g_agg + (size_t)grow * 128 + k0 + q * 4);
                float s = g_invdeg[grow];
                v.x *= s; v.y *= s; v.z *= s; v.w *= s;
            } else {
                v = *(const float4*)(X + (size_t)grow * 128 + (k0 - 128) + q * 4);
            }
            As[r][q * 4 + 0] = f2tf32(v.x);
            As[r][q * 4 + 1] = f2tf32(v.y);
            As[r][q * 4 + 2] = f2tf32(v.z);
            As[r][q * 4 + 3] = f2tf32(v.w);
        }

        const float* W = (k0 < 128) ? WN : WR;
        const int kk0 = k0 & 127;
#pragma unroll
        for (int i = 0; i < OUT / 32; i++) {
            int idx = i * 256 + tid;
            int o = idx >> 3, q = idx & 7;
            float4 v = *(const float4*)(W + (size_t)o * 128 + kk0 + q * 4);
            Bs[o][q * 4 + 0] = f2tf32(v.x);
            Bs[o][q * 4 + 1] = f2tf32(v.y);
            Bs[o][q * 4 + 2] = f2tf32(v.z);
            Bs[o][q * 4 + 3] = f2tf32(v.w);
        }
        __syncthreads();

#pragma unroll
        for (int ks = 0; ks < 4; ks++) {
            const int kk = ks * 8;
            uint32_t a[2][4];
#pragma unroll
            for (int m = 0; m < 2; m++) {
                int row = warp_m * 32 + m * 16 + g;
                a[m][0] = As[row][kk + t];
                a[m][1] = As[row + 8][kk + t];
                a[m][2] = As[row][kk + t + 4];
                a[m][3] = As[row + 8][kk + t + 4];
            }
            uint32_t b[NA][2];
#pragma unroll
            for (int n = 0; n < NA; n++) {
                int col = warp_n * (OUT / 2) + n * 8 + g;
                b[n][0] = Bs[col][kk + t];
                b[n][1] = Bs[col][kk + t + 4];
            }
#pragma unroll
            for (int m = 0; m < 2; m++)
#pragma unroll
                for (int n = 0; n < NA; n++)
                    mma_tf32(acc[m][n], a[m], b[n]);
        }
        __syncthreads();
    }

#pragma unroll
    for (int m = 0; m < 2; m++) {
        int r_lo = row0 + warp_m * 32 + m * 16 + g;
        int r_hi = r_lo + 8;
#pragma unroll
        for (int n = 0; n < NA; n++) {
            int col = warp_n * (OUT / 2) + n * 8 + t * 2;
            float bx = bias[col], by = bias[col + 1];
            float2 lo = make_float2(acc[m][n][0] + bx, acc[m][n][1] + by);
            float2 hi = make_float2(acc[m][n][2] + bx, acc[m][n][3] + by);
            if (RELU) {
                lo.x = fmaxf(lo.x, 0.f); lo.y = fmaxf(lo.y, 0.f);
                hi.x = fmaxf(hi.x, 0.f); hi.y = fmaxf(hi.y, 0.f);
            }
            if (r_lo < N_NODES) *(float2*)(Cout + (size_t)r_lo * OUT + col) = lo;
            if (r_hi < N_NODES) *(float2*)(Cout + (size_t)r_hi * OUT + col) = hi;
        }
    }
}

// ---------------- host launch ----------------
extern "C" void kernel_launch(void* const* d_in, const int* in_sizes, int n_in,
                              void* d_out, int out_size) {
    const float* x   = (const float*)d_in[0];
    const void*  ei  = d_in[1];
    const float* w1n = (const float*)d_in[2];
    const float* w1r = (const float*)d_in[3];
    const float* b1  = (const float*)d_in[4];
    const float* w2n = (const float*)d_in[5];
    const float* w2r = (const float*)d_in[6];
    const float* b2  = (const float*)d_in[7];
    const float* w3n = (const float*)d_in[8];
    const float* w3r = (const float*)d_in[9];
    const float* b3  = (const float*)d_in[10];
    float* out = (float*)d_out;

    float *agg, *deg, *h1, *h2;
    cudaGetSymbolAddress((void**)&agg, g_agg);
    cudaGetSymbolAddress((void**)&deg, g_deg);
    cudaGetSymbolAddress((void**)&h1,  g_h1);
    cudaGetSymbolAddress((void**)&h2,  g_h2);

    const int TPB = 256;
    const int edgeBlocks    = (N_EDGES + TPB - 1) / TPB;
    const int scatterBlocks = (N_EDGES * 32 + TPB - 1) / TPB;
    const int gemmBlocks    = (N_NODES + 127) / 128;

    detect_kernel<<<1, 256>>>((const unsigned int*)ei);
    convert_kernel<<<edgeBlocks, TPB>>>(ei);
    zero_kernel<<<64, TPB>>>(deg, 50048 / 4);
    deg_kernel<<<edgeBlocks, TPB>>>();
    invdeg_kernel<<<(N_NODES + TPB - 1) / TPB, TPB>>>();

    zero_kernel<<<512, TPB>>>(agg, (N_NODES * 128) / 4);
    scatter_kernel<<<scatterBlocks, TPB>>>(x);
    combine_mma<128, true><<<gemmBlocks, 256>>>(x, w1n, w1r, b1, h1);

    zero_kernel<<<512, TPB>>>(agg, (N_NODES * 128) / 4);
    scatter_kernel<<<scatterBlocks, TPB>>>(h1);
    combine_mma<128, true><<<gemmBlocks, 256>>>(h1, w2n, w2r, b2, h2);

    zero_kernel<<<512, TPB>>>(agg, (N_NODES * 128) / 4);
    scatter_kernel<<<scatterBlocks, TPB>>>(h2);
    combine_mma<64, false><<<gemmBlocks, 256>>>(h2, w3n, w3r, b3, out);
}

// round 4
// speedup vs baseline: 3.6088x; 1.5410x over previous
#include <cuda_runtime.h>
#include <cuda_bf16.h>
#include <cstdint>

#define N_NODES 50000
#define N_EDGES 600000

// ---------------- scratch (static __device__, no allocations) ----------------
__device__ int      g_src[N_EDGES];
__device__ int      g_dst[N_EDGES];
__device__ int      g_csr[N_EDGES];
__device__ int      g_ideg[50048];
__device__ int      g_rowptr[N_NODES + 1];
__device__ int      g_bsum[256];
__device__ int      g_cnt[50048];
__device__ uint32_t g_agg[(size_t)N_NODES * 128];   // tf32 bits, pre-scaled by 1/deg
__device__ uint32_t g_xtf[(size_t)N_NODES * 128];   // x converted to tf32 bits
__device__ float    g_h1[(size_t)N_NODES * 128];    // tf32-valued fp32
__device__ float    g_h2[(size_t)N_NODES * 128];
__device__ uint32_t g_B1[128 * 256];                // [o][k] tf32 bits, k = [wn | wr]
__device__ uint32_t g_B2[128 * 256];
__device__ uint32_t g_B3[64 * 256];
__device__ int      g_is64;

// ---------------- tf32 helpers ----------------
__device__ __forceinline__ uint32_t f2tf32(float f) {
    uint32_t o;
    asm("cvt.rna.tf32.f32 %0, %1;" : "=r"(o) : "f"(f));
    return o;
}
__device__ __forceinline__ void mma_tf32(float* d, const uint32_t* a, const uint32_t* b) {
    asm volatile(
        "mma.sync.aligned.m16n8k8.row.col.f32.tf32.tf32.f32 "
        "{%0,%1,%2,%3}, {%4,%5,%6,%7}, {%8,%9}, {%0,%1,%2,%3};"
        : "+f"(d[0]), "+f"(d[1]), "+f"(d[2]), "+f"(d[3])
        : "r"(a[0]), "r"(a[1]), "r"(a[2]), "r"(a[3]), "r"(b[0]), "r"(b[1]));
}

// ---------------- structure kernels ----------------
__global__ void zero_int_kernel(int* p, int n4) {
    int i = blockIdx.x * blockDim.x + threadIdx.x;
    int4 z = make_int4(0, 0, 0, 0);
    for (; i < n4; i += gridDim.x * blockDim.x) ((int4*)p)[i] = z;
}

__global__ void detect_kernel(const unsigned int* p) {
    __shared__ int cnt;
    if (threadIdx.x == 0) cnt = 0;
    __syncthreads();
    int local = 0;
    for (int i = threadIdx.x; i < 2048; i += blockDim.x)
        if (p[2 * i + 1] == 0u) local++;
    atomicAdd(&cnt, local);
    __syncthreads();
    if (threadIdx.x == 0) g_is64 = (cnt > 1024) ? 1 : 0;
}

__global__ void convert_kernel(const void* p) {
    int e = blockIdx.x * blockDim.x + threadIdx.x;
    if (e >= N_EDGES) return;
    if (g_is64) {
        const long long* q = (const long long*)p;
        g_src[e] = (int)q[e];
        g_dst[e] = (int)q[N_EDGES + e];
    } else {
        const int* q = (const int*)p;
        g_src[e] = q[e];
        g_dst[e] = q[N_EDGES + e];
    }
}

__global__ void deg_kernel() {
    int e = blockIdx.x * blockDim.x + threadIdx.x;
    if (e >= N_EDGES) return;
    atomicAdd(&g_ideg[g_dst[e]], 1);
}

// ---- 3-phase exclusive scan of g_ideg -> g_rowptr ----
__global__ void scan_local() {            // grid 196, block 256
    __shared__ int wtot[8];
    int b = blockIdx.x, t = threadIdx.x, i = b * 256 + t;
    int lane = t & 31, wid = t >> 5;
    int v = (i < N_NODES) ? g_ideg[i] : 0;
    int x = v;
#pragma unroll
    for (int o = 1; o < 32; o <<= 1) {
        int y = __shfl_up_sync(~0u, x, o);
        if (lane >= o) x += y;
    }
    if (lane == 31) wtot[wid] = x;
    __syncthreads();
    if (wid == 0) {
        int w = (lane < 8) ? wtot[lane] : 0;
#pragma unroll
        for (int o = 1; o < 8; o <<= 1) {
            int y = __shfl_up_sync(0xffffffffu, w, o);
            if (lane >= o) w += y;
        }
        if (lane < 8) wtot[lane] = w;
    }
    __syncthreads();
    int excl = x - v + (wid > 0 ? wtot[wid - 1] : 0);
    if (i < N_NODES) g_rowptr[i] = excl;
    if (t == 255) g_bsum[b] = excl + v;
}
__global__ void scan_bsums() {            // 1 block 256
    __shared__ int wtot[8];
    int t = threadIdx.x, lane = t & 31, wid = t >> 5;
    int v = (t < 196) ? g_bsum[t] : 0;
    int x = v;
#pragma unroll
    for (int o = 1; o < 32; o <<= 1) {
        int y = __shfl_up_sync(~0u, x, o);
        if (lane >= o) x += y;
    }
    if (lane == 31) wtot[wid] = x;
    __syncthreads();
    if (wid == 0) {
        int w = (lane < 8) ? wtot[lane] : 0;
#pragma unroll
        for (int o = 1; o < 8; o <<= 1) {
            int y = __shfl_up_sync(0xffffffffu, w, o);
            if (lane >= o) w += y;
        }
        if (lane < 8) wtot[lane] = w;
    }
    __syncthreads();
    g_bsum[t] = x - v + (wid > 0 ? wtot[wid - 1] : 0);
    if (t == 0) g_rowptr[N_NODES] = N_EDGES;
}
__global__ void scan_add() {              // grid 196
    int i = blockIdx.x * 256 + threadIdx.x;
    if (i < N_NODES) g_rowptr[i] += g_bsum[blockIdx.x];
}

__global__ void fill_csr() {
    int e = blockIdx.x * blockDim.x + threadIdx.x;
    if (e >= N_EDGES) return;
    int d = g_dst[e];
    int pos = atomicAdd(&g_cnt[d], 1);
    g_csr[g_rowptr[d] + pos] = g_src[e];
}

// ---------------- prep: fp32 -> tf32 bit conversion ----------------
__global__ void prepX_kernel(const float* __restrict__ x) {
    int i = blockIdx.x * blockDim.x + threadIdx.x;
    if (i < N_NODES * 128) g_xtf[i] = f2tf32(x[i]);
}
template <int OUT>
__global__ void prepB_kernel(const float* __restrict__ wn, const float* __restrict__ wr,
                             uint32_t* __restrict__ Bt) {
    int idx = blockIdx.x * blockDim.x + threadIdx.x;
    if (idx >= OUT * 256) return;
    int o = idx >> 8, k = idx & 255;
    float v = (k < 128) ? wn[o * 128 + k] : wr[o * 128 + (k - 128)];
    Bt[idx] = f2tf32(v);
}

// ---------------- gather-mean: one warp per node ----------------
__global__ void gather_mean(const float* __restrict__ X) {
    int w = (blockIdx.x * blockDim.x + threadIdx.x) >> 5;
    int lane = threadIdx.x & 31;
    if (w >= N_NODES) return;
    int beg = g_rowptr[w], end = g_rowptr[w + 1];
    float4 acc = make_float4(0.f, 0.f, 0.f, 0.f);
    int e = beg;
    for (; e + 4 <= end; e += 4) {
        int s0 = g_csr[e], s1 = g_csr[e + 1], s2 = g_csr[e + 2], s3 = g_csr[e + 3];
        float4 v0 = ((const float4*)(X + (size_t)s0 * 128))[lane];
        float4 v1 = ((const float4*)(X + (size_t)s1 * 128))[lane];
        float4 v2 = ((const float4*)(X + (size_t)s2 * 128))[lane];
        float4 v3 = ((const float4*)(X + (size_t)s3 * 128))[lane];
        acc.x += (v0.x + v1.x) + (v2.x + v3.x);
        acc.y += (v0.y + v1.y) + (v2.y + v3.y);
        acc.z += (v0.z + v1.z) + (v2.z + v3.z);
        acc.w += (v0.w + v1.w) + (v2.w + v3.w);
    }
    for (; e < end; e++) {
        float4 v = ((const float4*)(X + (size_t)g_csr[e] * 128))[lane];
        acc.x += v.x; acc.y += v.y; acc.z += v.z; acc.w += v.w;
    }
    float inv = 1.0f / fmaxf((float)(end - beg), 1.0f);
    uint4 o;
    o.x = f2tf32(acc.x * inv);
    o.y = f2tf32(acc.y * inv);
    o.z = f2tf32(acc.z * inv);
    o.w = f2tf32(acc.w * inv);
    ((uint4*)(g_agg + (size_t)w * 128))[lane] = o;
}

// ---------------- tensor-core combine GEMM (mma.sync tf32, reg-prefetch pipeline) ----------------
// C[i][o] = act( [agg_i | root_i] . Bw[o][0..255] + bias[o] )
template <int OUT, bool RELU, bool TFOUT>
__global__ void __launch_bounds__(256) combine_mma(
    const uint32_t* __restrict__ Aagg,
    const uint32_t* __restrict__ Aroot,
    const uint32_t* __restrict__ Bw,
    const float* __restrict__ bias,
    float* __restrict__ Cout)
{
    constexpr int NA = OUT / 16;
    constexpr int PB = OUT / 32;          // uint4 prefetch regs for B
    __shared__ uint32_t As[128][36];
    __shared__ uint32_t Bs[OUT][36];

    const int tid    = threadIdx.x;
    const int wid    = tid >> 5;
    const int lane   = tid & 31;
    const int warp_m = wid >> 1;
    const int warp_n = wid & 1;
    const int g      = lane >> 2;
    const int t      = lane & 3;
    const int row0   = blockIdx.x * 128;

    float acc[2][NA][4];
#pragma unroll
    for (int m = 0; m < 2; m++)
#pragma unroll
        for (int n = 0; n < NA; n++)
#pragma unroll
            for (int j = 0; j < 4; j++) acc[m][n][j] = 0.f;

    uint4 pa[4], pb[PB];

    auto loadA = [&](int c) {
        const int k0 = c * 32;
        const uint32_t* src = (k0 < 128) ? (Aagg + k0) : (Aroot + (k0 - 128));
#pragma unroll
        for (int i = 0; i < 4; i++) {
            int idx = i * 256 + tid;
            int r = idx >> 3, q = idx & 7;
            int grow = row0 + r;
            if (grow > N_NODES - 1) grow = N_NODES - 1;
            pa[i] = *(const uint4*)(src + (size_t)grow * 128 + q * 4);
        }
    };
    auto loadB = [&](int c) {
        const int k0 = c * 32;
#pragma unroll
        for (int i = 0; i < PB; i++) {
            int idx = i * 256 + tid;
            int o = idx >> 3, q = idx & 7;
            pb[i] = *(const uint4*)(Bw + (size_t)o * 256 + k0 + q * 4);
        }
    };

    loadA(0); loadB(0);

    for (int c = 0; c < 8; c++) {
        // store prefetched tiles to smem
#pragma unroll
        for (int i = 0; i < 4; i++) {
            int idx = i * 256 + tid;
            int r = idx >> 3, q = idx & 7;
            *(uint4*)&As[r][q * 4] = pa[i];
        }
#pragma unroll
        for (int i = 0; i < PB; i++) {
            int idx = i * 256 + tid;
            int o = idx >> 3, q = idx & 7;
            *(uint4*)&Bs[o][q * 4] = pb[i];
        }
        __syncthreads();

        if (c < 7) { loadA(c + 1); loadB(c + 1); }   // LDG latency hides behind mma

#pragma unroll
        for (int ks = 0; ks < 4; ks++) {
            const int kk = ks * 8;
            uint32_t a[2][4];
#pragma unroll
            for (int m = 0; m < 2; m++) {
                int row = warp_m * 32 + m * 16 + g;
                a[m][0] = As[row][kk + t];
                a[m][1] = As[row + 8][kk + t];
                a[m][2] = As[row][kk + t + 4];
                a[m][3] = As[row + 8][kk + t + 4];
            }
            uint32_t b[NA][2];
#pragma unroll
            for (int n = 0; n < NA; n++) {
                int col = warp_n * (OUT / 2) + n * 8 + g;
                b[n][0] = Bs[col][kk + t];
                b[n][1] = Bs[col][kk + t + 4];
            }
#pragma unroll
            for (int m = 0; m < 2; m++)
#pragma unroll
                for (int n = 0; n < NA; n++)
                    mma_tf32(acc[m][n], a[m], b[n]);
        }
        __syncthreads();
    }

    // ---- epilogue: bias + relu (+ tf32 round when feeding next layer) ----
#pragma unroll
    for (int m = 0; m < 2; m++) {
        int r_lo = row0 + warp_m * 32 + m * 16 + g;
        int r_hi = r_lo + 8;
#pragma unroll
        for (int n = 0; n < NA; n++) {
            int col = warp_n * (OUT / 2) + n * 8 + t * 2;
            float bx = bias[col], by = bias[col + 1];
            float v0 = acc[m][n][0] + bx, v1 = acc[m][n][1] + by;
            float v2 = acc[m][n][2] + bx, v3 = acc[m][n][3] + by;
            if (RELU) {
                v0 = fmaxf(v0, 0.f); v1 = fmaxf(v1, 0.f);
                v2 = fmaxf(v2, 0.f); v3 = fmaxf(v3, 0.f);
            }
            if (TFOUT) {
                v0 = __uint_as_float(f2tf32(v0)); v1 = __uint_as_float(f2tf32(v1));
                v2 = __uint_as_float(f2tf32(v2)); v3 = __uint_as_float(f2tf32(v3));
            }
            if (r_lo < N_NODES) *(float2*)(Cout + (size_t)r_lo * OUT + col) = make_float2(v0, v1);
            if (r_hi < N_NODES) *(float2*)(Cout + (size_t)r_hi * OUT + col) = make_float2(v2, v3);
        }
    }
}

// ---------------- host launch ----------------
extern "C" void kernel_launch(void* const* d_in, const int* in_sizes, int n_in,
                              void* d_out, int out_size) {
    const float* x   = (const float*)d_in[0];
    const void*  ei  = d_in[1];
    const float* w1n = (const float*)d_in[2];
    const float* w1r = (const float*)d_in[3];
    const float* b1  = (const float*)d_in[4];
    const float* w2n = (const float*)d_in[5];
    const float* w2r = (const float*)d_in[6];
    const float* b2  = (const float*)d_in[7];
    const float* w3n = (const float*)d_in[8];
    const float* w3r = (const float*)d_in[9];
    const float* b3  = (const float*)d_in[10];
    float* out = (float*)d_out;

    int *ideg, *cnt;
    uint32_t *xtf, *B1, *B2, *B3, *aggu, *h1u, *h2u;
    float *h1, *h2;
    cudaGetSymbolAddress((void**)&ideg, g_ideg);
    cudaGetSymbolAddress((void**)&cnt,  g_cnt);
    cudaGetSymbolAddress((void**)&xtf,  g_xtf);
    cudaGetSymbolAddress((void**)&B1,   g_B1);
    cudaGetSymbolAddress((void**)&B2,   g_B2);
    cudaGetSymbolAddress((void**)&B3,   g_B3);
    cudaGetSymbolAddress((void**)&aggu, g_agg);
    cudaGetSymbolAddress((void**)&h1,   g_h1);
    cudaGetSymbolAddress((void**)&h2,   g_h2);
    h1u = (uint32_t*)h1;
    h2u = (uint32_t*)h2;

    const int TPB = 256;
    const int edgeBlocks   = (N_EDGES + TPB - 1) / TPB;
    const int gatherBlocks = (N_NODES * 32 + TPB - 1) / TPB;   // 1 warp/node
    const int gemmBlocks   = (N_NODES + 127) / 128;            // 391
    const int featBlocks   = (N_NODES * 128 + TPB - 1) / TPB;

    // ---- structure + CSR (once per call) ----
    detect_kernel<<<1, 256>>>((const unsigned int*)ei);
    convert_kernel<<<edgeBlocks, TPB>>>(ei);
    zero_int_kernel<<<32, TPB>>>(ideg, 50048 / 4);
    zero_int_kernel<<<32, TPB>>>(cnt,  50048 / 4);
    deg_kernel<<<edgeBlocks, TPB>>>();
    scan_local<<<196, 256>>>();
    scan_bsums<<<1, 256>>>();
    scan_add<<<196, 256>>>();
    fill_csr<<<edgeBlocks, TPB>>>();

    // ---- one-time tf32 prep ----
    prepX_kernel<<<featBlocks, TPB>>>(x);
    prepB_kernel<128><<<(128 * 256 + TPB - 1) / TPB, TPB>>>(w1n, w1r, B1);
    prepB_kernel<128><<<(128 * 256 + TPB - 1) / TPB, TPB>>>(w2n, w2r, B2);
    prepB_kernel<64><<<(64 * 256 + TPB - 1) / TPB, TPB>>>(w3n, w3r, B3);

    // ---- layer 1 ----
    gather_mean<<<gatherBlocks, TPB>>>(x);
    combine_mma<128, true, true><<<gemmBlocks, 256>>>(aggu, xtf, B1, b1, h1);

    // ---- layer 2 ----
    gather_mean<<<gatherBlocks, TPB>>>(h1);
    combine_mma<128, true, true><<<gemmBlocks, 256>>>(aggu, h1u, B2, b2, h2);

    // ---- layer 3 ----
    gather_mean<<<gatherBlocks, TPB>>>(h2);
    combine_mma<64, false, false><<<gemmBlocks, 256>>>(aggu, h2u, B3, b3, out);
}

// round 5
// speedup vs baseline: 5.2776x; 1.4624x over previous
#include <cuda_runtime.h>
#include <cuda_fp16.h>
#include <cstdint>

#define N_NODES 50000
#define N_EDGES 600000

// ---------------- scratch (static __device__, no allocations) ----------------
__device__ int      g_src[N_EDGES];
__device__ int      g_dst[N_EDGES];
__device__ int      g_csr[N_EDGES];
__device__ int      g_ideg[50048];
__device__ int      g_rowptr[N_NODES + 1];
__device__ int      g_bsum[256];
__device__ int      g_cnt[50048];
__device__ uint16_t g_aggh[(size_t)N_NODES * 128];  // fp16 mean-aggregated features
__device__ uint16_t g_xh  [(size_t)N_NODES * 128];  // x in fp16
__device__ uint16_t g_h1h [(size_t)N_NODES * 128];  // hidden layers in fp16
__device__ uint16_t g_h2h [(size_t)N_NODES * 128];
__device__ uint16_t g_B1[128 * 256];                // [o][k] fp16, k = [wn | wr]
__device__ uint16_t g_B2[128 * 256];
__device__ uint16_t g_B3[64 * 256];
__device__ int      g_is64;

// ---------------- mma helper ----------------
__device__ __forceinline__ void mma_f16(float* d, const uint32_t* a, const uint32_t* b) {
    asm volatile(
        "mma.sync.aligned.m16n8k16.row.col.f32.f16.f16.f32 "
        "{%0,%1,%2,%3}, {%4,%5,%6,%7}, {%8,%9}, {%0,%1,%2,%3};"
        : "+f"(d[0]), "+f"(d[1]), "+f"(d[2]), "+f"(d[3])
        : "r"(a[0]), "r"(a[1]), "r"(a[2]), "r"(a[3]), "r"(b[0]), "r"(b[1]));
}

// ---------------- structure kernels ----------------
__global__ void zero2_kernel(int* p0, int* p1, int n4) {
    int i = blockIdx.x * blockDim.x + threadIdx.x;
    int4 z = make_int4(0, 0, 0, 0);
    for (; i < n4; i += gridDim.x * blockDim.x) { ((int4*)p0)[i] = z; ((int4*)p1)[i] = z; }
}

__global__ void detect_kernel(const unsigned int* p) {
    __shared__ int cnt;
    if (threadIdx.x == 0) cnt = 0;
    __syncthreads();
    int local = 0;
    for (int i = threadIdx.x; i < 2048; i += blockDim.x)
        if (p[2 * i + 1] == 0u) local++;
    atomicAdd(&cnt, local);
    __syncthreads();
    if (threadIdx.x == 0) g_is64 = (cnt > 1024) ? 1 : 0;
}

__global__ void convert_kernel(const void* p) {
    int e = blockIdx.x * blockDim.x + threadIdx.x;
    if (e >= N_EDGES) return;
    if (g_is64) {
        const long long* q = (const long long*)p;
        g_src[e] = (int)q[e];
        g_dst[e] = (int)q[N_EDGES + e];
    } else {
        const int* q = (const int*)p;
        g_src[e] = q[e];
        g_dst[e] = q[N_EDGES + e];
    }
}

__global__ void deg_kernel() {
    int e = blockIdx.x * blockDim.x + threadIdx.x;
    if (e >= N_EDGES) return;
    atomicAdd(&g_ideg[g_dst[e]], 1);
}

// ---- 3-phase exclusive scan of g_ideg -> g_rowptr ----
__global__ void scan_local() {            // grid 196, block 256
    __shared__ int wtot[8];
    int b = blockIdx.x, t = threadIdx.x, i = b * 256 + t;
    int lane = t & 31, wid = t >> 5;
    int v = (i < N_NODES) ? g_ideg[i] : 0;
    int x = v;
#pragma unroll
    for (int o = 1; o < 32; o <<= 1) {
        int y = __shfl_up_sync(~0u, x, o);
        if (lane >= o) x += y;
    }
    if (lane == 31) wtot[wid] = x;
    __syncthreads();
    if (wid == 0) {
        int w = (lane < 8) ? wtot[lane] : 0;
#pragma unroll
        for (int o = 1; o < 8; o <<= 1) {
            int y = __shfl_up_sync(0xffffffffu, w, o);
            if (lane >= o) w += y;
        }
        if (lane < 8) wtot[lane] = w;
    }
    __syncthreads();
    int excl = x - v + (wid > 0 ? wtot[wid - 1] : 0);
    if (i < N_NODES) g_rowptr[i] = excl;
    if (t == 255) g_bsum[b] = excl + v;
}
__global__ void scan_bsums() {            // 1 block 256
    __shared__ int wtot[8];
    int t = threadIdx.x, lane = t & 31, wid = t >> 5;
    int v = (t < 196) ? g_bsum[t] : 0;
    int x = v;
#pragma unroll
    for (int o = 1; o < 32; o <<= 1) {
        int y = __shfl_up_sync(~0u, x, o);
        if (lane >= o) x += y;
    }
    if (lane == 31) wtot[wid] = x;
    __syncthreads();
    if (wid == 0) {
        int w = (lane < 8) ? wtot[lane] : 0;
#pragma unroll
        for (int o = 1; o < 8; o <<= 1) {
            int y = __shfl_up_sync(0xffffffffu, w, o);
            if (lane >= o) w += y;
        }
        if (lane < 8) wtot[lane] = w;
    }
    __syncthreads();
    g_bsum[t] = x - v + (wid > 0 ? wtot[wid - 1] : 0);
    if (t == 0) g_rowptr[N_NODES] = N_EDGES;
}
__global__ void scan_add() {              // grid 196
    int i = blockIdx.x * 256 + threadIdx.x;
    if (i < N_NODES) g_rowptr[i] += g_bsum[blockIdx.x];
}

__global__ void fill_csr() {
    int e = blockIdx.x * blockDim.x + threadIdx.x;
    if (e >= N_EDGES) return;
    int d = g_dst[e];
    int pos = atomicAdd(&g_cnt[d], 1);
    g_csr[g_rowptr[d] + pos] = g_src[e];
}

// ---------------- prep: fp32 -> fp16 ----------------
__global__ void prepX_kernel(const float* __restrict__ x) {
    int i = blockIdx.x * blockDim.x + threadIdx.x;   // half2 granularity
    if (i >= N_NODES * 64) return;
    float2 v = ((const float2*)x)[i];
    ((__half2*)g_xh)[i] = __floats2half2_rn(v.x, v.y);
}
__global__ void prepB_kernel(const float* w1n, const float* w1r,
                             const float* w2n, const float* w2r,
                             const float* w3n, const float* w3r) {
    int idx = blockIdx.x * blockDim.x + threadIdx.x;
    // B1/B2: 128*256 each; B3: 64*256. total 81920
    if (idx < 32768) {
        int o = idx >> 8, k = idx & 255;
        float v = (k < 128) ? w1n[o * 128 + k] : w1r[o * 128 + (k - 128)];
        g_B1[idx] = __half_as_ushort(__float2half_rn(v));
    } else if (idx < 65536) {
        int j = idx - 32768;
        int o = j >> 8, k = j & 255;
        float v = (k < 128) ? w2n[o * 128 + k] : w2r[o * 128 + (k - 128)];
        g_B2[j] = __half_as_ushort(__float2half_rn(v));
    } else if (idx < 81920) {
        int j = idx - 65536;
        int o = j >> 8, k = j & 255;
        float v = (k < 128) ? w3n[o * 128 + k] : w3r[o * 128 + (k - 128)];
        g_B3[j] = __half_as_ushort(__float2half_rn(v));
    }
}

// ---------------- gather-mean (fp16 in, fp32 accum, fp16 out): one warp per node ----------------
__global__ void gather_mean(const uint16_t* __restrict__ Xh) {
    int w = (blockIdx.x * blockDim.x + threadIdx.x) >> 5;
    int lane = threadIdx.x & 31;
    if (w >= N_NODES) return;
    int beg = g_rowptr[w], end = g_rowptr[w + 1];
    float a0 = 0.f, a1 = 0.f, a2 = 0.f, a3 = 0.f;
    int e = beg;
    for (; e + 4 <= end; e += 4) {
        int s0 = g_csr[e], s1 = g_csr[e + 1], s2 = g_csr[e + 2], s3 = g_csr[e + 3];
        uint2 u0 = ((const uint2*)(Xh + (size_t)s0 * 128))[lane];
        uint2 u1 = ((const uint2*)(Xh + (size_t)s1 * 128))[lane];
        uint2 u2 = ((const uint2*)(Xh + (size_t)s2 * 128))[lane];
        uint2 u3 = ((const uint2*)(Xh + (size_t)s3 * 128))[lane];
        float2 f;
        f = __half22float2(*(__half2*)&u0.x); a0 += f.x; a1 += f.y;
        f = __half22float2(*(__half2*)&u0.y); a2 += f.x; a3 += f.y;
        f = __half22float2(*(__half2*)&u1.x); a0 += f.x; a1 += f.y;
        f = __half22float2(*(__half2*)&u1.y); a2 += f.x; a3 += f.y;
        f = __half22float2(*(__half2*)&u2.x); a0 += f.x; a1 += f.y;
        f = __half22float2(*(__half2*)&u2.y); a2 += f.x; a3 += f.y;
        f = __half22float2(*(__half2*)&u3.x); a0 += f.x; a1 += f.y;
        f = __half22float2(*(__half2*)&u3.y); a2 += f.x; a3 += f.y;
    }
    for (; e < end; e++) {
        uint2 u = ((const uint2*)(Xh + (size_t)g_csr[e] * 128))[lane];
        float2 f;
        f = __half22float2(*(__half2*)&u.x); a0 += f.x; a1 += f.y;
        f = __half22float2(*(__half2*)&u.y); a2 += f.x; a3 += f.y;
    }
    float inv = 1.0f / fmaxf((float)(end - beg), 1.0f);
    __half2 o0 = __floats2half2_rn(a0 * inv, a1 * inv);
    __half2 o1 = __floats2half2_rn(a2 * inv, a3 * inv);
    uint2 o;
    o.x = *(uint32_t*)&o0;
    o.y = *(uint32_t*)&o1;
    ((uint2*)(g_aggh + (size_t)w * 128))[lane] = o;
}

// ---------------- tensor-core combine GEMM (mma.sync fp16, reg-prefetch pipeline) ----------------
// C[i][o] = act( [agg_i | root_i] . Bw[o][0..255] + bias[o] )
// CTA tile 128 x OUT x 256; K chunked by 64 halves (4 chunks); 8 warps = 4(m) x 2(n).
template <int OUT, bool RELU, bool HOUT>
__global__ void __launch_bounds__(256) combine_mma(
    const uint16_t* __restrict__ Aagg,
    const uint16_t* __restrict__ Aroot,
    const uint16_t* __restrict__ Bw,
    const float* __restrict__ bias,
    void* __restrict__ Cout)
{
    constexpr int NA = OUT / 16;          // n-atoms per warp (8 / 4)
    constexpr int PB = OUT / 32;          // B prefetch uint4s per thread (4 / 2)
    __shared__ uint32_t As[128][36];      // 64 halves (32 u32) per row + pad
    __shared__ uint32_t Bs[OUT][36];

    const int tid    = threadIdx.x;
    const int wid    = tid >> 5;
    const int lane   = tid & 31;
    const int warp_m = wid >> 1;
    const int warp_n = wid & 1;
    const int g      = lane >> 2;
    const int t      = lane & 3;
    const int row0   = blockIdx.x * 128;

    float acc[2][NA][4];
#pragma unroll
    for (int m = 0; m < 2; m++)
#pragma unroll
        for (int n = 0; n < NA; n++)
#pragma unroll
            for (int j = 0; j < 4; j++) acc[m][n][j] = 0.f;

    uint4 pa[4], pb[PB];

    auto loadA = [&](int c) {
        const int k0 = c * 64;
        const uint16_t* src = (k0 < 128) ? (Aagg + k0) : (Aroot + (k0 - 128));
#pragma unroll
        for (int i = 0; i < 4; i++) {
            int idx = i * 256 + tid;
            int r = idx >> 3, q = idx & 7;          // q: 16B (8-half) slot
            int grow = row0 + r;
            if (grow > N_NODES - 1) grow = N_NODES - 1;
            pa[i] = *(const uint4*)(src + (size_t)grow * 128 + q * 8);
        }
    };
    auto loadB = [&](int c) {
        const int k0 = c * 64;
#pragma unroll
        for (int i = 0; i < PB; i++) {
            int idx = i * 256 + tid;
            int o = idx >> 3, q = idx & 7;
            pb[i] = *(const uint4*)(Bw + (size_t)o * 256 + k0 + q * 8);
        }
    };

    loadA(0); loadB(0);

    for (int c = 0; c < 4; c++) {
#pragma unroll
        for (int i = 0; i < 4; i++) {
            int idx = i * 256 + tid;
            int r = idx >> 3, q = idx & 7;
            *(uint4*)&As[r][q * 4] = pa[i];
        }
#pragma unroll
        for (int i = 0; i < PB; i++) {
            int idx = i * 256 + tid;
            int o = idx >> 3, q = idx & 7;
            *(uint4*)&Bs[o][q * 4] = pb[i];
        }
        __syncthreads();

        if (c < 3) { loadA(c + 1); loadB(c + 1); }   // LDG latency hides behind mma

#pragma unroll
        for (int ks = 0; ks < 4; ks++) {             // k16 steps within 64-half chunk
            const int off = ks * 8;                  // uint32 (half2) offset
            uint32_t a[2][4];
#pragma unroll
            for (int m = 0; m < 2; m++) {
                int row = warp_m * 32 + m * 16 + g;
                a[m][0] = As[row][off + t];
                a[m][1] = As[row + 8][off + t];
                a[m][2] = As[row][off + t + 4];
                a[m][3] = As[row + 8][off + t + 4];
            }
            uint32_t b[NA][2];
#pragma unroll
            for (int n = 0; n < NA; n++) {
                int col = warp_n * (OUT / 2) + n * 8 + g;
                b[n][0] = Bs[col][off + t];
                b[n][1] = Bs[col][off + t + 4];
            }
#pragma unroll
            for (int m = 0; m < 2; m++)
#pragma unroll
                for (int n = 0; n < NA; n++)
                    mma_f16(acc[m][n], a[m], b[n]);
        }
        __syncthreads();
    }

    // ---- epilogue: bias + relu; fp16 store for hidden layers, fp32 for output ----
#pragma unroll
    for (int m = 0; m < 2; m++) {
        int r_lo = row0 + warp_m * 32 + m * 16 + g;
        int r_hi = r_lo + 8;
#pragma unroll
        for (int n = 0; n < NA; n++) {
            int col = warp_n * (OUT / 2) + n * 8 + t * 2;
            float bx = bias[col], by = bias[col + 1];
            float v0 = acc[m][n][0] + bx, v1 = acc[m][n][1] + by;
            float v2 = acc[m][n][2] + bx, v3 = acc[m][n][3] + by;
            if (RELU) {
                v0 = fmaxf(v0, 0.f); v1 = fmaxf(v1, 0.f);
                v2 = fmaxf(v2, 0.f); v3 = fmaxf(v3, 0.f);
            }
            if (HOUT) {
                uint16_t* C = (uint16_t*)Cout;
                __half2 lo = __floats2half2_rn(v0, v1);
                __half2 hi = __floats2half2_rn(v2, v3);
                if (r_lo < N_NODES) *(uint32_t*)(C + (size_t)r_lo * OUT + col) = *(uint32_t*)&lo;
                if (r_hi < N_NODES) *(uint32_t*)(C + (size_t)r_hi * OUT + col) = *(uint32_t*)&hi;
            } else {
                float* C = (float*)Cout;
                if (r_lo < N_NODES) *(float2*)(C + (size_t)r_lo * OUT + col) = make_float2(v0, v1);
                if (r_hi < N_NODES) *(float2*)(C + (size_t)r_hi * OUT + col) = make_float2(v2, v3);
            }
        }
    }
}

// ---------------- host launch ----------------
extern "C" void kernel_launch(void* const* d_in, const int* in_sizes, int n_in,
                              void* d_out, int out_size) {
    const float* x   = (const float*)d_in[0];
    const void*  ei  = d_in[1];
    const float* w1n = (const float*)d_in[2];
    const float* w1r = (const float*)d_in[3];
    const float* b1  = (const float*)d_in[4];
    const float* w2n = (const float*)d_in[5];
    const float* w2r = (const float*)d_in[6];
    const float* b2  = (const float*)d_in[7];
    const float* w3n = (const float*)d_in[8];
    const float* w3r = (const float*)d_in[9];
    const float* b3  = (const float*)d_in[10];

    int *ideg, *cnt;
    uint16_t *xh, *aggh, *h1h, *h2h, *B1, *B2, *B3;
    cudaGetSymbolAddress((void**)&ideg, g_ideg);
    cudaGetSymbolAddress((void**)&cnt,  g_cnt);
    cudaGetSymbolAddress((void**)&xh,   g_xh);
    cudaGetSymbolAddress((void**)&aggh, g_aggh);
    cudaGetSymbolAddress((void**)&h1h,  g_h1h);
    cudaGetSymbolAddress((void**)&h2h,  g_h2h);
    cudaGetSymbolAddress((void**)&B1,   g_B1);
    cudaGetSymbolAddress((void**)&B2,   g_B2);
    cudaGetSymbolAddress((void**)&B3,   g_B3);

    const int TPB = 256;
    const int edgeBlocks   = (N_EDGES + TPB - 1) / TPB;
    const int gatherBlocks = (N_NODES * 32 + TPB - 1) / TPB;
    const int gemmBlocks   = (N_NODES + 127) / 128;

    // ---- structure + CSR ----
    detect_kernel<<<1, 256>>>((const unsigned int*)ei);
    convert_kernel<<<edgeBlocks, TPB>>>(ei);
    zero2_kernel<<<32, TPB>>>(ideg, cnt, 50048 / 4);
    deg_kernel<<<edgeBlocks, TPB>>>();
    scan_local<<<196, 256>>>();
    scan_bsums<<<1, 256>>>();
    scan_add<<<196, 256>>>();
    fill_csr<<<edgeBlocks, TPB>>>();

    // ---- fp16 prep ----
    prepX_kernel<<<(N_NODES * 64 + TPB - 1) / TPB, TPB>>>(x);
    prepB_kernel<<<(81920 + TPB - 1) / TPB, TPB>>>(w1n, w1r, w2n, w2r, w3n, w3r);

    // ---- layer 1 ----
    gather_mean<<<gatherBlocks, TPB>>>(xh);
    combine_mma<128, true, true><<<gemmBlocks, 256>>>(aggh, xh, B1, b1, h1h);

    // ---- layer 2 ----
    gather_mean<<<gatherBlocks, TPB>>>(h1h);
    combine_mma<128, true, true><<<gemmBlocks, 256>>>(aggh, h1h, B2, b2, h2h);

    // ---- layer 3 ----
    gather_mean<<<gatherBlocks, TPB>>>(h2h);
    combine_mma<64, false, false><<<gemmBlocks, 256>>>(aggh, h2h, B3, b3, d_out);
}

// round 6
// speedup vs baseline: 5.5323x; 1.0483x over previous
#include <cuda_runtime.h>
#include <cuda_fp16.h>
#include <cstdint>

#define N_NODES 50000
#define N_EDGES 600000

// ---------------- scratch (static __device__, no allocations) ----------------
__device__ int      g_src[N_EDGES];
__device__ int      g_dst[N_EDGES];
__device__ int      g_csr[N_EDGES];
__device__ int      g_ideg[50048];
__device__ int      g_rowptr[N_NODES + 1];
__device__ int      g_bsum[256];
__device__ int      g_cnt[50048];
__device__ uint16_t g_aggh[(size_t)N_NODES * 128];
__device__ uint16_t g_xh  [(size_t)N_NODES * 128];
__device__ uint16_t g_h1h [(size_t)N_NODES * 128];
__device__ uint16_t g_h2h [(size_t)N_NODES * 128];
__device__ uint16_t g_B1[128 * 256];
__device__ uint16_t g_B2[128 * 256];
__device__ uint16_t g_B3[64 * 256];
__device__ int      g_is64;

// ---------------- mma / cp.async helpers ----------------
__device__ __forceinline__ void mma_f16(float* d, const uint32_t* a, const uint32_t* b) {
    asm volatile(
        "mma.sync.aligned.m16n8k16.row.col.f32.f16.f16.f32 "
        "{%0,%1,%2,%3}, {%4,%5,%6,%7}, {%8,%9}, {%0,%1,%2,%3};"
        : "+f"(d[0]), "+f"(d[1]), "+f"(d[2]), "+f"(d[3])
        : "r"(a[0]), "r"(a[1]), "r"(a[2]), "r"(a[3]), "r"(b[0]), "r"(b[1]));
}
__device__ __forceinline__ void cp16(uint32_t smem, const void* g) {
    asm volatile("cp.async.ca.shared.global [%0], [%1], 16;" :: "r"(smem), "l"(g));
}
#define CP_COMMIT() asm volatile("cp.async.commit_group;")
#define CP_WAIT(N)  asm volatile("cp.async.wait_group %0;" :: "n"(N))

// ---------------- structure kernels ----------------
__global__ void zero2_kernel(int* p0, int* p1, int n4) {
    int i = blockIdx.x * blockDim.x + threadIdx.x;
    int4 z = make_int4(0, 0, 0, 0);
    for (; i < n4; i += gridDim.x * blockDim.x) { ((int4*)p0)[i] = z; ((int4*)p1)[i] = z; }
}

__global__ void detect_kernel(const unsigned int* p) {
    __shared__ int cnt;
    if (threadIdx.x == 0) cnt = 0;
    __syncthreads();
    int local = 0;
    for (int i = threadIdx.x; i < 2048; i += blockDim.x)
        if (p[2 * i + 1] == 0u) local++;
    atomicAdd(&cnt, local);
    __syncthreads();
    if (threadIdx.x == 0) g_is64 = (cnt > 1024) ? 1 : 0;
}

// convert (int64|int32 -> int32 src/dst) + degree histogram in one pass
__global__ void convert_deg_kernel(const void* p) {
    int e = blockIdx.x * blockDim.x + threadIdx.x;
    if (e >= N_EDGES) return;
    int s, d;
    if (g_is64) {
        const long long* q = (const long long*)p;
        s = (int)q[e];
        d = (int)q[N_EDGES + e];
    } else {
        const int* q = (const int*)p;
        s = q[e];
        d = q[N_EDGES + e];
    }
    g_src[e] = s;
    g_dst[e] = d;
    atomicAdd(&g_ideg[d], 1);
}

// ---- 3-phase exclusive scan of g_ideg -> g_rowptr ----
__global__ void scan_local() {            // grid 196, block 256
    __shared__ int wtot[8];
    int b = blockIdx.x, t = threadIdx.x, i = b * 256 + t;
    int lane = t & 31, wid = t >> 5;
    int v = (i < N_NODES) ? g_ideg[i] : 0;
    int x = v;
#pragma unroll
    for (int o = 1; o < 32; o <<= 1) {
        int y = __shfl_up_sync(~0u, x, o);
        if (lane >= o) x += y;
    }
    if (lane == 31) wtot[wid] = x;
    __syncthreads();
    if (wid == 0) {
        int w = (lane < 8) ? wtot[lane] : 0;
#pragma unroll
        for (int o = 1; o < 8; o <<= 1) {
            int y = __shfl_up_sync(0xffffffffu, w, o);
            if (lane >= o) w += y;
        }
        if (lane < 8) wtot[lane] = w;
    }
    __syncthreads();
    int excl = x - v + (wid > 0 ? wtot[wid - 1] : 0);
    if (i < N_NODES) g_rowptr[i] = excl;
    if (t == 255) g_bsum[b] = excl + v;
}
__global__ void scan_bsums() {            // 1 block 256
    __shared__ int wtot[8];
    int t = threadIdx.x, lane = t & 31, wid = t >> 5;
    int v = (t < 196) ? g_bsum[t] : 0;
    int x = v;
#pragma unroll
    for (int o = 1; o < 32; o <<= 1) {
        int y = __shfl_up_sync(~0u, x, o);
        if (lane >= o) x += y;
    }
    if (lane == 31) wtot[wid] = x;
    __syncthreads();
    if (wid == 0) {
        int w = (lane < 8) ? wtot[lane] : 0;
#pragma unroll
        for (int o = 1; o < 8; o <<= 1) {
            int y = __shfl_up_sync(0xffffffffu, w, o);
            if (lane >= o) w += y;
        }
        if (lane < 8) wtot[lane] = w;
    }
    __syncthreads();
    g_bsum[t] = x - v + (wid > 0 ? wtot[wid - 1] : 0);
    if (t == 0) g_rowptr[N_NODES] = N_EDGES;
}
__global__ void scan_add() {              // grid 196
    int i = blockIdx.x * 256 + threadIdx.x;
    if (i < N_NODES) g_rowptr[i] += g_bsum[blockIdx.x];
}

__global__ void fill_csr() {
    int e = blockIdx.x * blockDim.x + threadIdx.x;
    if (e >= N_EDGES) return;
    int d = g_dst[e];
    int pos = atomicAdd(&g_cnt[d], 1);
    g_csr[g_rowptr[d] + pos] = g_src[e];
}

// ---------------- prep: x and all weights -> fp16, one kernel ----------------
__global__ void prep_all(const float* __restrict__ x,
                         const float* w1n, const float* w1r,
                         const float* w2n, const float* w2r,
                         const float* w3n, const float* w3r) {
    int i = blockIdx.x * blockDim.x + threadIdx.x;
    const int NX = N_NODES * 64;                  // half2 count for x
    if (i < NX) {
        float2 v = ((const float2*)x)[i];
        ((__half2*)g_xh)[i] = __floats2half2_rn(v.x, v.y);
        return;
    }
    int idx = i - NX;
    if (idx < 32768) {
        int o = idx >> 8, k = idx & 255;
        float v = (k < 128) ? w1n[o * 128 + k] : w1r[o * 128 + (k - 128)];
        g_B1[idx] = __half_as_ushort(__float2half_rn(v));
    } else if (idx < 65536) {
        int j = idx - 32768;
        int o = j >> 8, k = j & 255;
        float v = (k < 128) ? w2n[o * 128 + k] : w2r[o * 128 + (k - 128)];
        g_B2[j] = __half_as_ushort(__float2half_rn(v));
    } else if (idx < 81920) {
        int j = idx - 65536;
        int o = j >> 8, k = j & 255;
        float v = (k < 128) ? w3n[o * 128 + k] : w3r[o * 128 + (k - 128)];
        g_B3[j] = __half_as_ushort(__float2half_rn(v));
    }
}

// ---------------- gather-mean: one warp per node, 2 half-warps x uint4 ----------------
__global__ void gather_mean(const uint16_t* __restrict__ Xh) {
    int w = (blockIdx.x * blockDim.x + threadIdx.x) >> 5;
    int lane = threadIdx.x & 31;
    if (w >= N_NODES) return;
    int beg = g_rowptr[w], end = g_rowptr[w + 1];
    int half = lane >> 4;        // which neighbor parity this lane covers
    int l16  = lane & 15;        // 16-byte slot within the 256B row

    float a[8];
#pragma unroll
    for (int j = 0; j < 8; j++) a[j] = 0.f;

    int e = beg + half;
    // unrolled: 2 neighbors in flight per half-warp (4 per warp)
    for (; e + 2 < end; e += 4) {
        int s0 = g_csr[e], s1 = g_csr[e + 2];
        uint4 u0 = ((const uint4*)(Xh + (size_t)s0 * 128))[l16];
        uint4 u1 = ((const uint4*)(Xh + (size_t)s1 * 128))[l16];
        float2 f;
        f = __half22float2(*(__half2*)&u0.x); a[0] += f.x; a[1] += f.y;
        f = __half22float2(*(__half2*)&u0.y); a[2] += f.x; a[3] += f.y;
        f = __half22float2(*(__half2*)&u0.z); a[4] += f.x; a[5] += f.y;
        f = __half22float2(*(__half2*)&u0.w); a[6] += f.x; a[7] += f.y;
        f = __half22float2(*(__half2*)&u1.x); a[0] += f.x; a[1] += f.y;
        f = __half22float2(*(__half2*)&u1.y); a[2] += f.x; a[3] += f.y;
        f = __half22float2(*(__half2*)&u1.z); a[4] += f.x; a[5] += f.y;
        f = __half22float2(*(__half2*)&u1.w); a[6] += f.x; a[7] += f.y;
    }
    for (; e < end; e += 2) {
        int s = g_csr[e];
        uint4 u = ((const uint4*)(Xh + (size_t)s * 128))[l16];
        float2 f;
        f = __half22float2(*(__half2*)&u.x); a[0] += f.x; a[1] += f.y;
        f = __half22float2(*(__half2*)&u.y); a[2] += f.x; a[3] += f.y;
        f = __half22float2(*(__half2*)&u.z); a[4] += f.x; a[5] += f.y;
        f = __half22float2(*(__half2*)&u.w); a[6] += f.x; a[7] += f.y;
    }
    // merge the two half-warps
#pragma unroll
    for (int j = 0; j < 8; j++) a[j] += __shfl_down_sync(~0u, a[j], 16);

    if (half == 0) {
        float inv = 1.0f / fmaxf((float)(end - beg), 1.0f);
        __half2 h0 = __floats2half2_rn(a[0] * inv, a[1] * inv);
        __half2 h1 = __floats2half2_rn(a[2] * inv, a[3] * inv);
        __half2 h2 = __floats2half2_rn(a[4] * inv, a[5] * inv);
        __half2 h3 = __floats2half2_rn(a[6] * inv, a[7] * inv);
        uint4 o;
        o.x = *(uint32_t*)&h0; o.y = *(uint32_t*)&h1;
        o.z = *(uint32_t*)&h2; o.w = *(uint32_t*)&h3;
        ((uint4*)(g_aggh + (size_t)w * 128))[l16] = o;
    }
}

// ---------------- tensor-core combine GEMM (mma.sync fp16 + cp.async double buffer) ----------------
template <int OUT, bool RELU, bool HOUT>
__global__ void __launch_bounds__(256) combine_mma(
    const uint16_t* __restrict__ Aagg,
    const uint16_t* __restrict__ Aroot,
    const uint16_t* __restrict__ Bw,
    const float* __restrict__ bias,
    void* __restrict__ Cout)
{
    constexpr int NA = OUT / 16;
    constexpr int PB = OUT / 32;
    __shared__ uint32_t As[2][128][36];
    __shared__ uint32_t Bs[2][OUT][36];

    const int tid    = threadIdx.x;
    const int wid    = tid >> 5;
    const int lane   = tid & 31;
    const int warp_m = wid >> 1;
    const int warp_n = wid & 1;
    const int g      = lane >> 2;
    const int t      = lane & 3;
    const int row0   = blockIdx.x * 128;

    float acc[2][NA][4];
#pragma unroll
    for (int m = 0; m < 2; m++)
#pragma unroll
        for (int n = 0; n < NA; n++)
#pragma unroll
            for (int j = 0; j < 4; j++) acc[m][n][j] = 0.f;

    auto issue = [&](int c, int buf) {
        const int k0 = c * 64;
        const uint16_t* src = (k0 < 128) ? (Aagg + k0) : (Aroot + (k0 - 128));
#pragma unroll
        for (int i = 0; i < 4; i++) {
            int idx = i * 256 + tid;
            int r = idx >> 3, q = idx & 7;
            int grow = row0 + r;
            if (grow > N_NODES - 1) grow = N_NODES - 1;
            cp16((uint32_t)__cvta_generic_to_shared(&As[buf][r][q * 4]),
                 src + (size_t)grow * 128 + q * 8);
        }
#pragma unroll
        for (int i = 0; i < PB; i++) {
            int idx = i * 256 + tid;
            int o = idx >> 3, q = idx & 7;
            cp16((uint32_t)__cvta_generic_to_shared(&Bs[buf][o][q * 4]),
                 Bw + (size_t)o * 256 + k0 + q * 8);
        }
        CP_COMMIT();
    };

    issue(0, 0);

    for (int c = 0; c < 4; c++) {
        if (c < 3) issue(c + 1, (c + 1) & 1);
        if (c < 3) { CP_WAIT(1); } else { CP_WAIT(0); }
        __syncthreads();

        const int buf = c & 1;
#pragma unroll
        for (int ks = 0; ks < 4; ks++) {
            const int off = ks * 8;
            uint32_t a[2][4];
#pragma unroll
            for (int m = 0; m < 2; m++) {
                int row = warp_m * 32 + m * 16 + g;
                a[m][0] = As[buf][row][off + t];
                a[m][1] = As[buf][row + 8][off + t];
                a[m][2] = As[buf][row][off + t + 4];
                a[m][3] = As[buf][row + 8][off + t + 4];
            }
            uint32_t b[NA][2];
#pragma unroll
            for (int n = 0; n < NA; n++) {
                int col = warp_n * (OUT / 2) + n * 8 + g;
                b[n][0] = Bs[buf][col][off + t];
                b[n][1] = Bs[buf][col][off + t + 4];
            }
#pragma unroll
            for (int m = 0; m < 2; m++)
#pragma unroll
                for (int n = 0; n < NA; n++)
                    mma_f16(acc[m][n], a[m], b[n]);
        }
        __syncthreads();
    }

    // ---- epilogue ----
#pragma unroll
    for (int m = 0; m < 2; m++) {
        int r_lo = row0 + warp_m * 32 + m * 16 + g;
        int r_hi = r_lo + 8;
#pragma unroll
        for (int n = 0; n < NA; n++) {
            int col = warp_n * (OUT / 2) + n * 8 + t * 2;
            float bx = bias[col], by = bias[col + 1];
            float v0 = acc[m][n][0] + bx, v1 = acc[m][n][1] + by;
            float v2 = acc[m][n][2] + bx, v3 = acc[m][n][3] + by;
            if (RELU) {
                v0 = fmaxf(v0, 0.f); v1 = fmaxf(v1, 0.f);
                v2 = fmaxf(v2, 0.f); v3 = fmaxf(v3, 0.f);
            }
            if (HOUT) {
                uint16_t* C = (uint16_t*)Cout;
                __half2 lo = __floats2half2_rn(v0, v1);
                __half2 hi = __floats2half2_rn(v2, v3);
                if (r_lo < N_NODES) *(uint32_t*)(C + (size_t)r_lo * OUT + col) = *(uint32_t*)&lo;
                if (r_hi < N_NODES) *(uint32_t*)(C + (size_t)r_hi * OUT + col) = *(uint32_t*)&hi;
            } else {
                float* C = (float*)Cout;
                if (r_lo < N_NODES) *(float2*)(C + (size_t)r_lo * OUT + col) = make_float2(v0, v1);
                if (r_hi < N_NODES) *(float2*)(C + (size_t)r_hi * OUT + col) = make_float2(v2, v3);
            }
        }
    }
}

// ---------------- host launch ----------------
extern "C" void kernel_launch(void* const* d_in, const int* in_sizes, int n_in,
                              void* d_out, int out_size) {
    const float* x   = (const float*)d_in[0];
    const void*  ei  = d_in[1];
    const float* w1n = (const float*)d_in[2];
    const float* w1r = (const float*)d_in[3];
    const float* b1  = (const float*)d_in[4];
    const float* w2n = (const float*)d_in[5];
    const float* w2r = (const float*)d_in[6];
    const float* b2  = (const float*)d_in[7];
    const float* w3n = (const float*)d_in[8];
    const float* w3r = (const float*)d_in[9];
    const float* b3  = (const float*)d_in[10];

    int *ideg, *cnt;
    uint16_t *xh, *aggh, *h1h, *h2h, *B1, *B2, *B3;
    cudaGetSymbolAddress((void**)&ideg, g_ideg);
    cudaGetSymbolAddress((void**)&cnt,  g_cnt);
    cudaGetSymbolAddress((void**)&xh,   g_xh);
    cudaGetSymbolAddress((void**)&aggh, g_aggh);
    cudaGetSymbolAddress((void**)&h1h,  g_h1h);
    cudaGetSymbolAddress((void**)&h2h,  g_h2h);
    cudaGetSymbolAddress((void**)&B1,   g_B1);
    cudaGetSymbolAddress((void**)&B2,   g_B2);
    cudaGetSymbolAddress((void**)&B3,   g_B3);

    const int TPB = 256;
    const int edgeBlocks   = (N_EDGES + TPB - 1) / TPB;
    const int gatherBlocks = (N_NODES * 32 + TPB - 1) / TPB;
    const int gemmBlocks   = (N_NODES + 127) / 128;
    const int prepBlocks   = (N_NODES * 64 + 81920 + TPB - 1) / TPB;

    // ---- structure + CSR ----
    detect_kernel<<<1, 256>>>((const unsigned int*)ei);
    zero2_kernel<<<32, TPB>>>(ideg, cnt, 50048 / 4);
    convert_deg_kernel<<<edgeBlocks, TPB>>>(ei);
    scan_local<<<196, 256>>>();
    scan_bsums<<<1, 256>>>();
    scan_add<<<196, 256>>>();
    fill_csr<<<edgeBlocks, TPB>>>();

    // ---- fp16 prep (x + all weights) ----
    prep_all<<<prepBlocks, TPB>>>(x, w1n, w1r, w2n, w2r, w3n, w3r);

    // ---- layer 1 ----
    gather_mean<<<gatherBlocks, TPB>>>(xh);
    combine_mma<128, true, true><<<gemmBlocks, 256>>>(aggh, xh, B1, b1, h1h);

    // ---- layer 2 ----
    gather_mean<<<gatherBlocks, TPB>>>(h1h);
    combine_mma<128, true, true><<<gemmBlocks, 256>>>(aggh, h1h, B2, b2, h2h);

    // ---- layer 3 ----
    gather_mean<<<gatherBlocks, TPB>>>(h2h);
    combine_mma<64, false, false><<<gemmBlocks, 256>>>(aggh, h2h, B3, b3, d_out);
}

// round 8
// speedup vs baseline: 5.6884x; 1.0282x over previous
#include <cuda_runtime.h>
#include <cuda_fp16.h>
#include <cstdint>

#define N_NODES 50000
#define N_EDGES 600000

// ---------------- scratch (static __device__, no allocations) ----------------
__device__ int      g_src[N_EDGES];
__device__ int      g_dst[N_EDGES];
__device__ int      g_csr[N_EDGES];
__device__ int      g_ideg[50048];
__device__ int      g_rowptr[N_NODES + 1];
__device__ int      g_bsum[256];
__device__ int      g_cnt[50048];
__device__ uint16_t g_aggh[(size_t)N_NODES * 128];
__device__ uint16_t g_xh  [(size_t)N_NODES * 128];
__device__ uint16_t g_h1h [(size_t)N_NODES * 128];
__device__ uint16_t g_h2h [(size_t)N_NODES * 128];
__device__ uint16_t g_B1[128 * 256];
__device__ uint16_t g_B2[128 * 256];
__device__ uint16_t g_B3[64 * 256];
__device__ int      g_is64;

// ---------------- mma / cp.async helpers ----------------
__device__ __forceinline__ void mma_f16(float* d, const uint32_t* a, const uint32_t* b) {
    asm volatile(
        "mma.sync.aligned.m16n8k16.row.col.f32.f16.f16.f32 "
        "{%0,%1,%2,%3}, {%4,%5,%6,%7}, {%8,%9}, {%0,%1,%2,%3};"
        : "+f"(d[0]), "+f"(d[1]), "+f"(d[2]), "+f"(d[3])
        : "r"(a[0]), "r"(a[1]), "r"(a[2]), "r"(a[3]), "r"(b[0]), "r"(b[1]));
}
__device__ __forceinline__ void cp16(uint32_t smem, const void* g) {
    asm volatile("cp.async.ca.shared.global [%0], [%1], 16;" :: "r"(smem), "l"(g));
}
#define CP_COMMIT() asm volatile("cp.async.commit_group;")
#define CP_WAIT(N)  asm volatile("cp.async.wait_group %0;" :: "n"(N))

// ---------------- structure kernels ----------------
// blocks 0..31: zero ideg+cnt; block 32: dtype sniffer
__global__ void zero_detect(const unsigned int* p) {
    if (blockIdx.x == 32) {
        __shared__ int cnt;
        if (threadIdx.x == 0) cnt = 0;
        __syncthreads();
        int local = 0;
        for (int i = threadIdx.x; i < 2048; i += blockDim.x)
            if (p[2 * i + 1] == 0u) local++;
        atomicAdd(&cnt, local);
        __syncthreads();
        if (threadIdx.x == 0) g_is64 = (cnt > 1024) ? 1 : 0;
        return;
    }
    int i = blockIdx.x * blockDim.x + threadIdx.x;
    int4 z = make_int4(0, 0, 0, 0);
    for (; i < 50048 / 4; i += 32 * blockDim.x) {
        ((int4*)g_ideg)[i] = z;
        ((int4*)g_cnt)[i]  = z;
    }
}

// merged: edge convert + degree histogram  ||  fp16 prep of x and all weights
#define EDGE_BLOCKS 2344
__global__ void convert_deg_prep(const void* p, const float* __restrict__ x,
                                 const float* w1n, const float* w1r,
                                 const float* w2n, const float* w2r,
                                 const float* w3n, const float* w3r) {
    int b = blockIdx.x;
    if (b < EDGE_BLOCKS) {
        int e = b * blockDim.x + threadIdx.x;
        if (e >= N_EDGES) return;
        int s, d;
        if (g_is64) {
            const long long* q = (const long long*)p;
            s = (int)q[e];
            d = (int)q[N_EDGES + e];
        } else {
            const int* q = (const int*)p;
            s = q[e];
            d = q[N_EDGES + e];
        }
        g_src[e] = s;
        g_dst[e] = d;
        atomicAdd(&g_ideg[d], 1);
        return;
    }
    int i = (b - EDGE_BLOCKS) * blockDim.x + threadIdx.x;
    const int NX = N_NODES * 64;                  // half2 count for x
    if (i < NX) {
        float2 v = ((const float2*)x)[i];
        ((__half2*)g_xh)[i] = __floats2half2_rn(v.x, v.y);
        return;
    }
    int idx = i - NX;
    if (idx < 32768) {
        int o = idx >> 8, k = idx & 255;
        float v = (k < 128) ? w1n[o * 128 + k] : w1r[o * 128 + (k - 128)];
        g_B1[idx] = __half_as_ushort(__float2half_rn(v));
    } else if (idx < 65536) {
        int j = idx - 32768;
        int o = j >> 8, k = j & 255;
        float v = (k < 128) ? w2n[o * 128 + k] : w2r[o * 128 + (k - 128)];
        g_B2[j] = __half_as_ushort(__float2half_rn(v));
    } else if (idx < 81920) {
        int j = idx - 65536;
        int o = j >> 8, k = j & 255;
        float v = (k < 128) ? w3n[o * 128 + k] : w3r[o * 128 + (k - 128)];
        g_B3[j] = __half_as_ushort(__float2half_rn(v));
    }
}

// ---- 3-phase exclusive scan of g_ideg -> g_rowptr ----
__global__ void scan_local() {            // grid 196, block 256
    __shared__ int wtot[8];
    int b = blockIdx.x, t = threadIdx.x, i = b * 256 + t;
    int lane = t & 31, wid = t >> 5;
    int v = (i < N_NODES) ? g_ideg[i] : 0;
    int x = v;
#pragma unroll
    for (int o = 1; o < 32; o <<= 1) {
        int y = __shfl_up_sync(~0u, x, o);
        if (lane >= o) x += y;
    }
    if (lane == 31) wtot[wid] = x;
    __syncthreads();
    if (wid == 0) {
        int w = (lane < 8) ? wtot[lane] : 0;
#pragma unroll
        for (int o = 1; o < 8; o <<= 1) {
            int y = __shfl_up_sync(0xffffffffu, w, o);
            if (lane >= o) w += y;
        }
        if (lane < 8) wtot[lane] = w;
    }
    __syncthreads();
    int excl = x - v + (wid > 0 ? wtot[wid - 1] : 0);
    if (i < N_NODES) g_rowptr[i] = excl;
    if (t == 255) g_bsum[b] = excl + v;
}
__global__ void scan_bsums() {            // 1 block 256
    __shared__ int wtot[8];
    int t = threadIdx.x, lane = t & 31, wid = t >> 5;
    int v = (t < 196) ? g_bsum[t] : 0;
    int x = v;
#pragma unroll
    for (int o = 1; o < 32; o <<= 1) {
        int y = __shfl_up_sync(~0u, x, o);
        if (lane >= o) x += y;
    }
    if (lane == 31) wtot[wid] = x;
    __syncthreads();
    if (wid == 0) {
        int w = (lane < 8) ? wtot[lane] : 0;
#pragma unroll
        for (int o = 1; o < 8; o <<= 1) {
            int y = __shfl_up_sync(0xffffffffu, w, o);
            if (lane >= o) w += y;
        }
        if (lane < 8) wtot[lane] = w;
    }
    __syncthreads();
    g_bsum[t] = x - v + (wid > 0 ? wtot[wid - 1] : 0);
    if (t == 0) g_rowptr[N_NODES] = N_EDGES;
}
__global__ void scan_add() {              // grid 196
    int i = blockIdx.x * 256 + threadIdx.x;
    if (i < N_NODES) g_rowptr[i] += g_bsum[blockIdx.x];
}

__global__ void fill_csr() {
    int e = blockIdx.x * blockDim.x + threadIdx.x;
    if (e >= N_EDGES) return;
    int d = g_dst[e];
    int pos = atomicAdd(&g_cnt[d], 1);
    g_csr[g_rowptr[d] + pos] = g_src[e];
}

// ---------------- gather-mean: one warp per node, 2 half-warps, 4-deep MLP ----------------
__global__ void gather_mean(const uint16_t* __restrict__ Xh) {
    int w = (blockIdx.x * blockDim.x + threadIdx.x) >> 5;
    int lane = threadIdx.x & 31;
    if (w >= N_NODES) return;
    int beg = g_rowptr[w], end = g_rowptr[w + 1];
    int half = lane >> 4;
    int l16  = lane & 15;

    float a[8];
#pragma unroll
    for (int j = 0; j < 8; j++) a[j] = 0.f;

    int e = beg + half;
    // 4 neighbors in flight per half-warp (8 edges per warp iteration)
    for (; e + 6 < end; e += 8) {
        int s0 = g_csr[e],     s1 = g_csr[e + 2];
        int s2 = g_csr[e + 4], s3 = g_csr[e + 6];
        uint4 u0 = ((const uint4*)(Xh + (size_t)s0 * 128))[l16];
        uint4 u1 = ((const uint4*)(Xh + (size_t)s1 * 128))[l16];
        uint4 u2 = ((const uint4*)(Xh + (size_t)s2 * 128))[l16];
        uint4 u3 = ((const uint4*)(Xh + (size_t)s3 * 128))[l16];
        float2 f;
        f = __half22float2(*(__half2*)&u0.x); a[0] += f.x; a[1] += f.y;
        f = __half22float2(*(__half2*)&u0.y); a[2] += f.x; a[3] += f.y;
        f = __half22float2(*(__half2*)&u0.z); a[4] += f.x; a[5] += f.y;
        f = __half22float2(*(__half2*)&u0.w); a[6] += f.x; a[7] += f.y;
        f = __half22float2(*(__half2*)&u1.x); a[0] += f.x; a[1] += f.y;
        f = __half22float2(*(__half2*)&u1.y); a[2] += f.x; a[3] += f.y;
        f = __half22float2(*(__half2*)&u1.z); a[4] += f.x; a[5] += f.y;
        f = __half22float2(*(__half2*)&u1.w); a[6] += f.x; a[7] += f.y;
        f = __half22float2(*(__half2*)&u2.x); a[0] += f.x; a[1] += f.y;
        f = __half22float2(*(__half2*)&u2.y); a[2] += f.x; a[3] += f.y;
        f = __half22float2(*(__half2*)&u2.z); a[4] += f.x; a[5] += f.y;
        f = __half22float2(*(__half2*)&u2.w); a[6] += f.x; a[7] += f.y;
        f = __half22float2(*(__half2*)&u3.x); a[0] += f.x; a[1] += f.y;
        f = __half22float2(*(__half2*)&u3.y); a[2] += f.x; a[3] += f.y;
        f = __half22float2(*(__half2*)&u3.z); a[4] += f.x; a[5] += f.y;
        f = __half22float2(*(__half2*)&u3.w); a[6] += f.x; a[7] += f.y;
    }
    for (; e < end; e += 2) {
        int s = g_csr[e];
        uint4 u = ((const uint4*)(Xh + (size_t)s * 128))[l16];
        float2 f;
        f = __half22float2(*(__half2*)&u.x); a[0] += f.x; a[1] += f.y;
        f = __half22float2(*(__half2*)&u.y); a[2] += f.x; a[3] += f.y;
        f = __half22float2(*(__half2*)&u.z); a[4] += f.x; a[5] += f.y;
        f = __half22float2(*(__half2*)&u.w); a[6] += f.x; a[7] += f.y;
    }
#pragma unroll
    for (int j = 0; j < 8; j++) a[j] += __shfl_down_sync(~0u, a[j], 16);

    if (half == 0) {
        float inv = 1.0f / fmaxf((float)(end - beg), 1.0f);
        __half2 h0 = __floats2half2_rn(a[0] * inv, a[1] * inv);
        __half2 h1 = __floats2half2_rn(a[2] * inv, a[3] * inv);
        __half2 h2 = __floats2half2_rn(a[4] * inv, a[5] * inv);
        __half2 h3 = __floats2half2_rn(a[6] * inv, a[7] * inv);
        uint4 o;
        o.x = *(uint32_t*)&h0; o.y = *(uint32_t*)&h1;
        o.z = *(uint32_t*)&h2; o.w = *(uint32_t*)&h3;
        ((uint4*)(g_aggh + (size_t)w * 128))[l16] = o;
    }
}

// ---------------- persistent tensor-core combine (M-tile 64, 4 warps, cp.async db) ----------------
template <int OUT, bool RELU, bool HOUT>
__global__ void __launch_bounds__(128, 4) combine_mma(
    const uint16_t* __restrict__ Aagg,
    const uint16_t* __restrict__ Aroot,
    const uint16_t* __restrict__ Bw,
    const float* __restrict__ bias,
    void* __restrict__ Cout)
{
    constexpr int NA = OUT / 16;
    constexpr int NTILES = (N_NODES + 63) / 64;   // 782
    __shared__ uint32_t As[2][64][36];
    __shared__ uint32_t Bs[2][OUT][36];

    const int tid    = threadIdx.x;
    const int wid    = tid >> 5;
    const int lane   = tid & 31;
    const int warp_m = wid >> 1;       // 0..1
    const int warp_n = wid & 1;        // 0..1
    const int g      = lane >> 2;
    const int t      = lane & 3;

    for (int tile = blockIdx.x; tile < NTILES; tile += gridDim.x) {
        const int row0 = tile * 64;

        float acc[2][NA][4];
#pragma unroll
        for (int m = 0; m < 2; m++)
#pragma unroll
            for (int n = 0; n < NA; n++)
#pragma unroll
                for (int j = 0; j < 4; j++) acc[m][n][j] = 0.f;

        auto issue = [&](int c, int buf) {
            const int k0 = c * 64;
            const uint16_t* src = (k0 < 128) ? (Aagg + k0) : (Aroot + (k0 - 128));
#pragma unroll
            for (int i = 0; i < 4; i++) {          // A: 512 uint4 / 128 thr
                int idx = i * 128 + tid;
                int r = idx >> 3, q = idx & 7;
                int grow = row0 + r;
                if (grow > N_NODES - 1) grow = N_NODES - 1;
                cp16((uint32_t)__cvta_generic_to_shared(&As[buf][r][q * 4]),
                     src + (size_t)grow * 128 + q * 8);
            }
#pragma unroll
            for (int i = 0; i < OUT / 16; i++) {   // B: OUT*8 uint4 / 128 thr
                int idx = i * 128 + tid;
                int o = idx >> 3, q = idx & 7;
                cp16((uint32_t)__cvta_generic_to_shared(&Bs[buf][o][q * 4]),
                     Bw + (size_t)o * 256 + k0 + q * 8);
            }
            CP_COMMIT();
        };

        issue(0, 0);

        for (int c = 0; c < 4; c++) {
            if (c < 3) { issue(c + 1, (c + 1) & 1); CP_WAIT(1); }
            else       { CP_WAIT(0); }
            __syncthreads();

            const int buf = c & 1;
#pragma unroll
            for (int ks = 0; ks < 4; ks++) {
                const int off = ks * 8;
                uint32_t a[2][4];
#pragma unroll
                for (int m = 0; m < 2; m++) {
                    int row = warp_m * 32 + m * 16 + g;
                    a[m][0] = As[buf][row][off + t];
                    a[m][1] = As[buf][row + 8][off + t];
                    a[m][2] = As[buf][row][off + t + 4];
                    a[m][3] = As[buf][row + 8][off + t + 4];
                }
                uint32_t b[NA][2];
#pragma unroll
                for (int n = 0; n < NA; n++) {
                    int col = warp_n * (OUT / 2) + n * 8 + g;
                    b[n][0] = Bs[buf][col][off + t];
                    b[n][1] = Bs[buf][col][off + t + 4];
                }
#pragma unroll
                for (int m = 0; m < 2; m++)
#pragma unroll
                    for (int n = 0; n < NA; n++)
                        mma_f16(acc[m][n], a[m], b[n]);
            }
            __syncthreads();
        }

        // ---- epilogue (registers only; safe to overlap with next tile's cp.async) ----
#pragma unroll
        for (int m = 0; m < 2; m++) {
            int r_lo = row0 + warp_m * 32 + m * 16 + g;
            int r_hi = r_lo + 8;
#pragma unroll
            for (int n = 0; n < NA; n++) {
                int col = warp_n * (OUT / 2) + n * 8 + t * 2;
                float bx = bias[col], by = bias[col + 1];
                float v0 = acc[m][n][0] + bx, v1 = acc[m][n][1] + by;
                float v2 = acc[m][n][2] + bx, v3 = acc[m][n][3] + by;
                if (RELU) {
                    v0 = fmaxf(v0, 0.f); v1 = fmaxf(v1, 0.f);
                    v2 = fmaxf(v2, 0.f); v3 = fmaxf(v3, 0.f);
                }
                if (HOUT) {
                    uint16_t* C = (uint16_t*)Cout;
                    __half2 lo = __floats2half2_rn(v0, v1);
                    __half2 hi = __floats2half2_rn(v2, v3);
                    if (r_lo < N_NODES) *(uint32_t*)(C + (size_t)r_lo * OUT + col) = *(uint32_t*)&lo;
                    if (r_hi < N_NODES) *(uint32_t*)(C + (size_t)r_hi * OUT + col) = *(uint32_t*)&hi;
                } else {
                    float* C = (float*)Cout;
                    if (r_lo < N_NODES) *(float2*)(C + (size_t)r_lo * OUT + col) = make_float2(v0, v1);
                    if (r_hi < N_NODES) *(float2*)(C + (size_t)r_hi * OUT + col) = make_float2(v2, v3);
                }
            }
        }
    }
}

// ---------------- host launch ----------------
extern "C" void kernel_launch(void* const* d_in, const int* in_sizes, int n_in,
                              void* d_out, int out_size) {
    const float* x   = (const float*)d_in[0];
    const void*  ei  = d_in[1];
    const float* w1n = (const float*)d_in[2];
    const float* w1r = (const float*)d_in[3];
    const float* b1  = (const float*)d_in[4];
    const float* w2n = (const float*)d_in[5];
    const float* w2r = (const float*)d_in[6];
    const float* b2  = (const float*)d_in[7];
    const float* w3n = (const float*)d_in[8];
    const float* w3r = (const float*)d_in[9];
    const float* b3  = (const float*)d_in[10];

    uint16_t *xh, *aggh, *h1h, *h2h, *B1, *B2, *B3;
    cudaGetSymbolAddress((void**)&xh,   g_xh);
    cudaGetSymbolAddress((void**)&aggh, g_aggh);
    cudaGetSymbolAddress((void**)&h1h,  g_h1h);
    cudaGetSymbolAddress((void**)&h2h,  g_h2h);
    cudaGetSymbolAddress((void**)&B1,   g_B1);
    cudaGetSymbolAddress((void**)&B2,   g_B2);
    cudaGetSymbolAddress((void**)&B3,   g_B3);

    const int TPB = 256;
    const int gatherBlocks = (N_NODES * 32 + TPB - 1) / TPB;
    const int prepBlocks   = (N_NODES * 64 + 81920 + TPB - 1) / TPB;   // 12820
    const int gemm128Grid  = 592;   // 4 CTAs/SM x 148 SMs, persistent loop over 782 tiles
    const int gemm64Grid   = 782;   // single wave (6 CTAs/SM possible at 36.9KB smem)

    // ---- structure + CSR + prep ----
    zero_detect<<<33, TPB>>>((const unsigned int*)ei);
    convert_deg_prep<<<EDGE_BLOCKS + prepBlocks, TPB>>>(ei, x, w1n, w1r, w2n, w2r, w3n, w3r);
    scan_local<<<196, 256>>>();
    scan_bsums<<<1, 256>>>();
    scan_add<<<196, 256>>>();
    fill_csr<<<EDGE_BLOCKS, TPB>>>();

    // ---- layer 1 ----
    gather_mean<<<gatherBlocks, TPB>>>(xh);
    combine_mma<128, true, true><<<gemm128Grid, 128>>>(aggh, xh, B1, b1, h1h);

    // ---- layer 2 ----
    gather_mean<<<gatherBlocks, TPB>>>(h1h);
    combine_mma<128, true, true><<<gemm128Grid, 128>>>(aggh, h1h, B2, b2, h2h);

    // ---- layer 3 ----
    gather_mean<<<gatherBlocks, TPB>>>(h2h);
    combine_mma<64, false, false><<<gemm64Grid, 128>>>(aggh, h2h, B3, b3, d_out);
}